// round 1
// baseline (speedup 1.0000x reference)
#include <cuda_runtime.h>
#include <stdint.h>

// Problem constants (match reference)
#define BS 32
#define N 512
#define IN_X 16
#define IN_E 5
#define IN_C 3
#define IN_BD 3
#define OUT_X 16
#define OUT_E 5
#define OUT_C 3
#define OUT_BD 3

// Output layout (floats), concatenated in reference-tuple order
#define XCAT_OFF   0
#define XCAT_SZ    (BS * N * (IN_X + OUT_X))          // 524288
#define CCAT_OFF   (XCAT_OFF + XCAT_SZ)               // 524288
#define CCAT_SZ    (BS * N * (IN_C + OUT_C))          // 98304
#define E1_OFF     (CCAT_OFF + CCAT_SZ)               // 622592
#define E1_SZ      (BS * N * N * OUT_E)               // 41943040
#define E2_OFF     (E1_OFF + E1_SZ)                   // 42565632
#define E2_SZ      (BS * N * N * OUT_E)
#define BD1_OFF    (E2_OFF + E2_SZ)                   // 84508672
#define BD1_SZ     (BS * N * N * OUT_BD)              // 25165824

// prodpos[i*N+j] = product position aligned to reactant slot j, or -1 if unmapped
__device__ int g_prodpos[BS * N];

// ---------------------------------------------------------------------------
// Kernel 1: alignment map. One block per sample, N threads.
// ---------------------------------------------------------------------------
__global__ void prep_kernel(const int* __restrict__ amn_in,
                            const int* __restrict__ ma_in) {
    __shared__ int s_max;
    __shared__ int s_table[N + 1];   // table[m] = product pos + 1 (0 = absent)
    const int i = blockIdx.x;
    const int j = threadIdx.x;

    const int amn = amn_in[i * N + j];
    const int ma  = ma_in[i * N + j];

    if (j == 0) s_max = -2147483647;
    s_table[j] = 0;
    if (j == 0) s_table[N] = 0;
    __syncthreads();

    atomicMax(&s_max, ma);
    __syncthreads();
    const int pa = s_max;

    // product-side scatter: table[amn] = j+1 for product atoms
    if (ma == pa && amn > 0 && amn <= N) {
        s_table[amn] = j + 1;
    }
    __syncthreads();

    // reactant-side lookup
    int pp = -1;
    if (ma < pa && amn > 0 && amn <= N) {
        int t = s_table[amn];
        if (t > 0) pp = t - 1;
    }
    g_prodpos[i * N + j] = pp;
}

// ---------------------------------------------------------------------------
// Kernel 2: node features (X_cat, C_cat). Grid-stride over 622592 floats.
// ---------------------------------------------------------------------------
__global__ void node_kernel(const float* __restrict__ X,
                            const float* __restrict__ AC,
                            float* __restrict__ out) {
    const int total = XCAT_SZ + CCAT_SZ;
    for (int o = blockIdx.x * blockDim.x + threadIdx.x; o < total;
         o += gridDim.x * blockDim.x) {
        if (o < XCAT_SZ) {
            const int c = o & 31;                 // 32 channels
            const int row = o >> 5;               // i*N + j
            float v;
            if (c < IN_X) {
                v = X[row * IN_X + c];
            } else {
                const int p = g_prodpos[row];
                const int i = row >> 9;           // row / N
                v = (p >= 0) ? X[(i * N + p) * IN_X + (c - IN_X)] : 0.0f;
            }
            out[XCAT_OFF + o] = v;
        } else {
            const int o2 = o - XCAT_SZ;
            const int c = o2 % 6;
            const int row = o2 / 6;
            float v;
            if (c < IN_C) {
                v = AC[row * IN_C + c];
            } else {
                const int p = g_prodpos[row];
                const int i = row >> 9;
                v = (p >= 0) ? AC[(i * N + p) * IN_C + (c - IN_C)] : 0.0f;
            }
            out[CCAT_OFF + o2] = v;
        }
    }
}

// ---------------------------------------------------------------------------
// Kernel 3: edge features. One block per (i, j1). 256 threads.
//   Writes E1 row (N*5), E2 row (N*5), BD1 row (N*3).
// ---------------------------------------------------------------------------
__global__ __launch_bounds__(256) void edge_kernel(const float* __restrict__ E,
                                                   const float* __restrict__ BD,
                                                   float* __restrict__ out) {
    __shared__ int sp[N];
    const int b  = blockIdx.x;
    const int i  = b >> 9;        // b / N
    const int j1 = b & (N - 1);
    const int tid = threadIdx.x;

    // load prodpos row for this sample
    #pragma unroll
    for (int k = 0; k < N / 256; k++) {
        sp[tid + k * 256] = g_prodpos[i * N + tid + k * 256];
    }
    __syncthreads();

    const int p1 = sp[j1];
    const long long row = (long long)b;   // i*N + j1
    float* __restrict__ e1r = out + E1_OFF  + row * (N * OUT_E);
    float* __restrict__ e2r = out + E2_OFF  + row * (N * OUT_E);
    float* __restrict__ bdr = out + BD1_OFF + row * (N * OUT_BD);

    if (p1 < 0) {
        // Unmapped row: pure fills, vectorized.
        const float4 z4 = make_float4(0.f, 0.f, 0.f, 0.f);
        float4 pat[5];
        pat[0] = make_float4(1.f, 0.f, 0.f, 0.f);
        pat[1] = make_float4(0.f, 1.f, 0.f, 0.f);
        pat[2] = make_float4(0.f, 0.f, 1.f, 0.f);
        pat[3] = make_float4(0.f, 0.f, 0.f, 1.f);
        pat[4] = z4;
        float4* e1v = reinterpret_cast<float4*>(e1r);
        float4* e2v = reinterpret_cast<float4*>(e2r);
        float4* bdv = reinterpret_cast<float4*>(bdr);
        #pragma unroll
        for (int k = tid; k < (N * OUT_E) / 4; k += 256) {   // 640 vecs
            e1v[k] = z4;
            e2v[k] = pat[k % 5];
        }
        #pragma unroll
        for (int k = tid; k < (N * OUT_BD) / 4; k += 256) {  // 384 vecs
            bdv[k] = z4;
        }
        return;
    }

    // Mapped row: gather product edges.
    const float* __restrict__ Erow  = E  + ((long long)(i * N + p1) * N) * IN_E;
    const float* __restrict__ BDrow = BD + ((long long)(i * N + p1) * N) * IN_BD;

    for (int idx = tid; idx < N * OUT_E; idx += 256) {       // 2560 floats
        const int j2 = idx / 5;
        const int c  = idx - j2 * 5;
        const int p2 = sp[j2];
        float v1, v2;
        if (p2 >= 0) {
            v1 = __ldg(&Erow[p2 * IN_E + c]);
            v2 = 0.0f;
        } else {
            v1 = 0.0f;
            v2 = (c == 0) ? 1.0f : 0.0f;
        }
        e1r[idx] = v1;
        e2r[idx] = v2;
    }
    for (int idx = tid; idx < N * OUT_BD; idx += 256) {      // 1536 floats
        const int j2 = idx / 3;
        const int c  = idx - j2 * 3;
        const int p2 = sp[j2];
        bdr[idx] = (p2 >= 0) ? __ldg(&BDrow[p2 * IN_BD + c]) : 0.0f;
    }
}

// ---------------------------------------------------------------------------
extern "C" void kernel_launch(void* const* d_in, const int* in_sizes, int n_in,
                              void* d_out, int out_size) {
    const float* X   = (const float*)d_in[0];
    const float* E   = (const float*)d_in[1];
    const float* AC  = (const float*)d_in[2];
    const float* BD  = (const float*)d_in[3];
    const int*   AMN = (const int*)d_in[4];
    const int*   MA  = (const int*)d_in[5];
    float* out = (float*)d_out;

    prep_kernel<<<BS, N>>>(AMN, MA);
    node_kernel<<<1216, 256>>>(X, AC, out);
    edge_kernel<<<BS * N, 256>>>(E, BD, out);
}

// round 2
// speedup vs baseline: 1.0627x; 1.0627x over previous
#include <cuda_runtime.h>
#include <stdint.h>

#define BS 32
#define N 512
#define IN_X 16
#define IN_E 5
#define IN_C 3
#define IN_BD 3
#define OUT_X 16
#define OUT_E 5
#define OUT_C 3
#define OUT_BD 3

// Output layout (floats), concatenated in reference-tuple order
#define XCAT_OFF   0
#define XCAT_SZ    (BS * N * (IN_X + OUT_X))          // 524288
#define CCAT_OFF   (XCAT_OFF + XCAT_SZ)
#define CCAT_SZ    (BS * N * (IN_C + OUT_C))          // 98304
#define E1_OFF     (CCAT_OFF + CCAT_SZ)               // 622592
#define E1_SZ      (BS * N * N * OUT_E)               // 41943040
#define E2_OFF     (E1_OFF + E1_SZ)
#define BD1_OFF    (E2_OFF + E1_SZ)

// ---------------------------------------------------------------------------
// Fully fused kernel: one block per (sample i, reactant row j1).
// Each block rebuilds the per-sample alignment map in smem (inputs are tiny
// and L2-resident), writes its node-feature rows, and its three edge rows.
// ---------------------------------------------------------------------------
__global__ __launch_bounds__(256) void fused_kernel(
    const float* __restrict__ X,
    const float* __restrict__ E,
    const float* __restrict__ AC,
    const float* __restrict__ BD,
    const int*   __restrict__ AMN,
    const int*   __restrict__ MA,
    float* __restrict__ out)
{
    __shared__ int s_amn[N];
    __shared__ int s_ma[N];
    __shared__ int s_table[N + 1];   // table[m] = product pos + 1 (0 = absent)
    __shared__ int s_sp[N];          // prodpos per reactant slot (built lazily)
    __shared__ int s_max;

    const int b   = blockIdx.x;
    const int i   = b >> 9;          // sample
    const int j1  = b & (N - 1);     // row
    const int tid = threadIdx.x;

    // ---- per-sample alignment prep (redundant per block; L2-cached inputs) --
    if (tid == 0) { s_max = -2147483647; s_table[N] = 0; }
    int mymax = -2147483647;
    #pragma unroll
    for (int k = 0; k < N / 256; k++) {
        const int j = tid + k * 256;
        const int a = AMN[i * N + j];
        const int m = MA[i * N + j];
        s_amn[j] = a;
        s_ma[j]  = m;
        s_table[j] = 0;              // zero table[0..N-1]
        mymax = max(mymax, m);
    }
    #pragma unroll
    for (int off = 16; off; off >>= 1)
        mymax = max(mymax, __shfl_xor_sync(0xffffffffu, mymax, off));
    __syncthreads();
    if ((tid & 31) == 0) atomicMax(&s_max, mymax);
    __syncthreads();
    const int pa = s_max;

    // product-side scatter: table[amn] = j+1
    #pragma unroll
    for (int k = 0; k < N / 256; k++) {
        const int j = tid + k * 256;
        const int a = s_amn[j];
        if (s_ma[j] == pa && a > 0 && a <= N) s_table[a] = j + 1;
    }
    __syncthreads();

    // this row's aligned product position
    int p1 = -1;
    {
        const int a = s_amn[j1];
        if (s_ma[j1] < pa && a > 0 && a <= N) {
            const int t = s_table[a];
            if (t > 0) p1 = t - 1;
        }
    }

    const int row = b;               // i*N + j1
    float* __restrict__ e1r = out + E1_OFF  + (size_t)row * (N * OUT_E);
    float* __restrict__ e2r = out + E2_OFF  + (size_t)row * (N * OUT_E);
    float* __restrict__ bdr = out + BD1_OFF + (size_t)row * (N * OUT_BD);

    // ---- node features for this row (38 floats) ----
    if (tid < 32) {
        float v;
        if (tid < IN_X) v = X[row * IN_X + tid];
        else            v = (p1 >= 0) ? __ldg(&X[(i * N + p1) * IN_X + (tid - IN_X)]) : 0.0f;
        out[XCAT_OFF + row * (IN_X + OUT_X) + tid] = v;
    } else if (tid < 38) {
        const int c = tid - 32;
        float v;
        if (c < IN_C) v = AC[row * IN_C + c];
        else          v = (p1 >= 0) ? __ldg(&AC[(i * N + p1) * IN_C + (c - IN_C)]) : 0.0f;
        out[CCAT_OFF + row * (IN_C + OUT_C) + c] = v;
    }

    float4* __restrict__ e1v = reinterpret_cast<float4*>(e1r);
    float4* __restrict__ e2v = reinterpret_cast<float4*>(e2r);
    float4* __restrict__ bdv = reinterpret_cast<float4*>(bdr);

    if (p1 < 0) {
        // ---- unmapped row: pure vectorized fills ----
        const float4 z4 = make_float4(0.f, 0.f, 0.f, 0.f);
        float4 pat[5];
        pat[0] = make_float4(1.f, 0.f, 0.f, 0.f);
        pat[1] = make_float4(0.f, 1.f, 0.f, 0.f);
        pat[2] = make_float4(0.f, 0.f, 1.f, 0.f);
        pat[3] = make_float4(0.f, 0.f, 0.f, 1.f);
        pat[4] = z4;
        #pragma unroll
        for (int k = tid; k < (N * OUT_E) / 4; k += 256) {   // 640 vecs
            __stcs(&e1v[k], z4);
            __stcs(&e2v[k], pat[k % 5]);
        }
        #pragma unroll
        for (int k = tid; k < (N * OUT_BD) / 4; k += 256) {  // 384 vecs
            __stcs(&bdv[k], z4);
        }
        return;
    }

    // ---- mapped row: build full sp table, then vectorized gather+store ----
    #pragma unroll
    for (int k = 0; k < N / 256; k++) {
        const int j = tid + k * 256;
        const int a = s_amn[j];
        int pp = -1;
        if (s_ma[j] < pa && a > 0 && a <= N) {
            const int t = s_table[a];
            if (t > 0) pp = t - 1;
        }
        s_sp[j] = pp;
    }
    __syncthreads();

    const float* __restrict__ Erow  = E  + (size_t)(i * N + p1) * N * IN_E;
    const float* __restrict__ BDrow = BD + (size_t)(i * N + p1) * N * IN_BD;

    // E1 / E2: 640 float4 per row
    for (int k = tid; k < (N * OUT_E) / 4; k += 256) {
        float v1[4], v2[4];
        const int e0 = 4 * k;
        #pragma unroll
        for (int c4 = 0; c4 < 4; c4++) {
            const int ee = e0 + c4;
            const int j2 = ee / 5;
            const int c  = ee - j2 * 5;
            const int p2 = s_sp[j2];
            if (p2 >= 0) {
                v1[c4] = __ldg(&Erow[p2 * IN_E + c]);
                v2[c4] = 0.0f;
            } else {
                v1[c4] = 0.0f;
                v2[c4] = (c == 0) ? 1.0f : 0.0f;
            }
        }
        __stcs(&e1v[k], make_float4(v1[0], v1[1], v1[2], v1[3]));
        __stcs(&e2v[k], make_float4(v2[0], v2[1], v2[2], v2[3]));
    }

    // BD1: 384 float4 per row
    for (int k = tid; k < (N * OUT_BD) / 4; k += 256) {
        float v[4];
        const int e0 = 4 * k;
        #pragma unroll
        for (int c4 = 0; c4 < 4; c4++) {
            const int ee = e0 + c4;
            const int j2 = ee / 3;
            const int c  = ee - j2 * 3;
            const int p2 = s_sp[j2];
            v[c4] = (p2 >= 0) ? __ldg(&BDrow[p2 * IN_BD + c]) : 0.0f;
        }
        __stcs(&bdv[k], make_float4(v[0], v[1], v[2], v[3]));
    }
}

// ---------------------------------------------------------------------------
extern "C" void kernel_launch(void* const* d_in, const int* in_sizes, int n_in,
                              void* d_out, int out_size) {
    const float* X   = (const float*)d_in[0];
    const float* E   = (const float*)d_in[1];
    const float* AC  = (const float*)d_in[2];
    const float* BD  = (const float*)d_in[3];
    const int*   AMN = (const int*)d_in[4];
    const int*   MA  = (const int*)d_in[5];
    float* out = (float*)d_out;

    fused_kernel<<<BS * N, 256>>>(X, E, AC, BD, AMN, MA, out);
}